// round 2
// baseline (speedup 1.0000x reference)
#include <cuda_runtime.h>
#include <cuda_bf16.h>
#include <math.h>

#define B_   256
#define IN_  64
#define HID_ 128
#define OUT_ 64
#define T_   1000

// ---------------- device scratch (static, allocation-free) ----------------
__device__ float g_xeff[(size_t)B_ * IN_ * T_];   // (b, i, t) effective x
__device__ float g_gxT [(size_t)B_ * IN_ * T_];   // (b, n, t) gamma_x
// per (b,t): [0:128)=gamma_h  [128:256)=A_z  [256:384)=A_r  [384:512)=A_h
__device__ float g_act [(size_t)B_ * T_ * 512];
__device__ float g_wzrh[128 * 384];               // packed [x;m] -> [z|r|h]
__device__ float g_bzrh[384];

__device__ __forceinline__ float sigf(float x) { return 1.0f / (1.0f + __expf(-x)); }
__device__ __forceinline__ float tanhfast(float x) {
    float e = __expf(-2.0f * fabsf(x));
    float r = (1.0f - e) / (1.0f + e);
    return copysignf(r, x);
}

// ---------------- pack combined [x;m] weights -----------------------------
__global__ void pack_kernel(const float* __restrict__ Wxz, const float* __restrict__ Wmz,
                            const float* __restrict__ bmz,
                            const float* __restrict__ Wxr, const float* __restrict__ Wmr,
                            const float* __restrict__ Wxh, const float* __restrict__ Wmh,
                            const float* __restrict__ bmh) {
    for (int idx = threadIdx.x; idx < 128 * 384; idx += blockDim.x) {
        int k = idx / 384, n = idx % 384;
        int mat = n >> 7, j = n & 127;
        const float* Wx = (mat == 0) ? Wxz : ((mat == 1) ? Wxr : Wxh);
        const float* Wm = (mat == 0) ? Wmz : ((mat == 1) ? Wmr : Wmh);
        g_wzrh[idx] = (k < 64) ? Wx[k * 128 + j] : Wm[(k - 64) * 128 + j];
    }
    for (int n = threadIdx.x; n < 384; n += blockDim.x) {
        int mat = n >> 7, j = n & 127;
        g_bzrh[n] = (mat == 0) ? bmz[j] : ((mat == 2) ? bmh[j] : 0.0f);
    }
}

// ---------------- GEMM over feature-major A -------------------------------
// C[b][t][n] = sum_f A[b][f][t] * W[f][n]  (+bias, +activation)
// srcMode 0: A0 = Ain + 2*IN*T (d channel), stride 3*IN*T (K<=64)
// srcMode 1: A0 = g_xeff (stride IN*T), A1 = Ain + IN*T (m ch), W/bias = packed
// outMode 0: g_act at outOff      outMode 1: g_gxT (b,n,t)
__global__ __launch_bounds__(256)
void gemmT_kernel(const float* __restrict__ Ain,
                  const float* __restrict__ W_in, int ldw,
                  const float* __restrict__ bias_in,
                  int K, int actMode, int outMode, int outOff, int srcMode) {
    __shared__ float As[16 * 132];
    __shared__ float Bs[16 * 64];
    const float* Wp = srcMode ? g_wzrh : W_in;
    const float* bp = srcMode ? g_bzrh : bias_in;
    int b  = blockIdx.z;
    int t0 = blockIdx.y * 128;
    int n0 = blockIdx.x * 64;
    int tid = threadIdx.x;
    int f_l = tid >> 4, v = tid & 15;
    int ty  = tid >> 4, tx = tid & 15;

    float acc[8][4];
#pragma unroll
    for (int i = 0; i < 8; i++)
#pragma unroll
        for (int j = 0; j < 4; j++) acc[i][j] = 0.0f;

    for (int kbase = 0; kbase < K; kbase += 16) {
        int f = kbase + f_l;
        const float* rowp;
        if (srcMode == 0) {
            rowp = Ain + (size_t)2 * IN_ * T_ + (size_t)b * 3 * IN_ * T_ + (size_t)f * T_;
        } else {
            rowp = (f < 64) ? (g_xeff + (size_t)b * IN_ * T_ + (size_t)f * T_)
                            : (Ain + (size_t)IN_ * T_ + (size_t)b * 3 * IN_ * T_ + (size_t)(f - 64) * T_);
        }
#pragma unroll
        for (int h = 0; h < 2; ++h) {
            int tg = t0 + (v + 16 * h) * 4;
            float4 av = make_float4(0.f, 0.f, 0.f, 0.f);
            if (tg < T_) av = *(const float4*)(rowp + tg);
            *(float4*)&As[f_l * 132 + (v + 16 * h) * 4] = av;
        }
        *(float4*)&Bs[f_l * 64 + v * 4] =
            *(const float4*)(Wp + (size_t)(kbase + f_l) * ldw + n0 + v * 4);
        __syncthreads();
#pragma unroll
        for (int kk = 0; kk < 16; ++kk) {
            float4 a0q = *(float4*)&As[kk * 132 + ty * 8];
            float4 a1q = *(float4*)&As[kk * 132 + ty * 8 + 4];
            float4 bq  = *(float4*)&Bs[kk * 64 + tx * 4];
            float a[8] = {a0q.x, a0q.y, a0q.z, a0q.w, a1q.x, a1q.y, a1q.z, a1q.w};
            float bb[4] = {bq.x, bq.y, bq.z, bq.w};
#pragma unroll
            for (int i = 0; i < 8; i++)
#pragma unroll
                for (int j = 0; j < 4; j++) acc[i][j] = fmaf(a[i], bb[j], acc[i][j]);
        }
        __syncthreads();
    }
    float bl[4];
#pragma unroll
    for (int j = 0; j < 4; j++) bl[j] = bp[n0 + tx * 4 + j];
#pragma unroll
    for (int i = 0; i < 8; i++) {
        int tg = t0 + ty * 8 + i;
        if (tg >= T_) continue;
        float vv[4];
#pragma unroll
        for (int j = 0; j < 4; j++) {
            float x = acc[i][j] + bl[j];
            if (actMode == 1) x = __expf(-fmaxf(x, 0.0f));
            vv[j] = x;
        }
        if (outMode == 0) {
            *(float4*)(g_act + ((size_t)b * T_ + tg) * 512 + outOff + n0 + tx * 4) =
                make_float4(vv[0], vv[1], vv[2], vv[3]);
        } else {
#pragma unroll
            for (int j = 0; j < 4; j++)
                g_gxT[((size_t)b * 64 + n0 + tx * 4 + j) * T_ + tg] = vv[j];
        }
    }
}

// ---------------- LOCF scan + effective-x ---------------------------------
__global__ void scan_kernel(const float* __restrict__ input, const float* __restrict__ x_mean) {
    int tid = blockIdx.x * blockDim.x + threadIdx.x;  // 0 .. B*IN-1
    int b = tid >> 6, i = tid & 63;
    const float4* Xp = (const float4*)(input + ((size_t)(b * 3 + 0) * IN_ + i) * T_);
    const float4* Mp = (const float4*)(input + ((size_t)(b * 3 + 1) * IN_ + i) * T_);
    const float4* Gp = (const float4*)(g_gxT + ((size_t)b * IN_ + i) * T_);
    float4*       Op = (float4*)(g_xeff + ((size_t)b * IN_ + i) * T_);
    float xm = x_mean[i];
    float xl = 0.0f;
    for (int v = 0; v < T_ / 4; ++v) {
        float4 x4 = Xp[v], m4 = Mp[v], g4 = Gp[v];
        float4 o;
        if (m4.x > 0.f) { xl = x4.x; o.x = x4.x; } else { o.x = g4.x * xl + (1.f - g4.x) * xm; }
        if (m4.y > 0.f) { xl = x4.y; o.y = x4.y; } else { o.y = g4.y * xl + (1.f - g4.y) * xm; }
        if (m4.z > 0.f) { xl = x4.z; o.z = x4.z; } else { o.z = g4.z * xl + (1.f - g4.z) * xm; }
        if (m4.w > 0.f) { xl = x4.w; o.w = x4.w; } else { o.w = g4.w * xl + (1.f - g4.w) * xm; }
        Op[v] = o;
    }
}

// ---------------- persistent recurrence: 2 batch rows per CTA --------------
// 128 threads; thread tid owns output column j=tid for BOTH rows.
__global__ __launch_bounds__(128, 1)
void recur_kernel(const float* __restrict__ Whz, const float* __restrict__ Whr,
                  const float* __restrict__ Whh, float* __restrict__ out) {
    extern __shared__ float sm[];
    float* Wz   = sm;                  // 128*132
    float* Wr   = Wz + 128 * 132;
    float* Wh   = Wr + 128 * 132;
    float* hbuf = Wh + 128 * 132;      // 2 bufs x 2 rows x 128
    float* rbuf = hbuf + 2 * 2 * 128;  // 2 bufs x 2 rows x 128

    int tid = threadIdx.x;
    int b0 = blockIdx.x * 2, b1 = b0 + 1;

    // load + transpose weights: Wt[j*132 + k] = W[k*128 + j]
    for (int idx = tid; idx < 128 * 128; idx += 128) {
        int k = idx >> 7, j = idx & 127;
        Wz[j * 132 + k] = Whz[idx];
        Wr[j * 132 + k] = Whr[idx];
        Wh[j * 132 + k] = Whh[idx];
    }
    __syncthreads();

    float* hs = out + (size_t)B_ * T_ * OUT_;  // hs region of d_out

    const float* act0 = g_act + (size_t)b0 * T_ * 512 + tid;
    const float* act1 = g_act + (size_t)b1 * T_ * 512 + tid;

    float h0 = 0.f, h1 = 0.f;
    float gh0 = act0[0], az0 = act0[128], ar0 = act0[256], ah0 = act0[384];
    float gh1 = act1[0], az1 = act1[128], ar1 = act1[256], ah1 = act1[384];

    const float4* wz4 = (const float4*)(Wz + tid * 132);
    const float4* wr4 = (const float4*)(Wr + tid * 132);
    const float4* wh4 = (const float4*)(Wh + tid * 132);

    for (int t = 0; t < T_; ++t) {
        int p = t & 1;
        float* hq = hbuf + p * 256;
        float* hp = rbuf + p * 256;

        float hh0 = gh0 * h0;
        float hh1 = gh1 * h1;
        hq[tid] = hh0;
        hq[128 + tid] = hh1;

        // prefetch next step's activations
        float ngh0 = gh0, naz0 = az0, nar0 = ar0, nah0 = ah0;
        float ngh1 = gh1, naz1 = az1, nar1 = ar1, nah1 = ah1;
        if (t + 1 < T_) {
            const float* a0 = act0 + (size_t)(t + 1) * 512;
            const float* a1 = act1 + (size_t)(t + 1) * 512;
            ngh0 = a0[0]; naz0 = a0[128]; nar0 = a0[256]; nah0 = a0[384];
            ngh1 = a1[0]; naz1 = a1[128]; nar1 = a1[256]; nah1 = a1[384];
        }
        __syncthreads();

        // z / r GEMVs (fused over k), 16 independent accumulator chains
        float za0 = az0, zb0 = 0.f, zc0 = 0.f, zd0 = 0.f;
        float za1 = az1, zb1 = 0.f, zc1 = 0.f, zd1 = 0.f;
        float ra0 = ar0, rb0 = 0.f, rc0 = 0.f, rd0 = 0.f;
        float ra1 = ar1, rb1 = 0.f, rc1 = 0.f, rd1 = 0.f;
        const float4* h0v = (const float4*)hq;
        const float4* h1v = (const float4*)(hq + 128);
#pragma unroll
        for (int k4 = 0; k4 < 32; ++k4) {
            float4 wz = wz4[k4], wr = wr4[k4];
            float4 a0 = h0v[k4], a1 = h1v[k4];
            za0 = fmaf(wz.x, a0.x, za0); zb0 = fmaf(wz.y, a0.y, zb0);
            zc0 = fmaf(wz.z, a0.z, zc0); zd0 = fmaf(wz.w, a0.w, zd0);
            za1 = fmaf(wz.x, a1.x, za1); zb1 = fmaf(wz.y, a1.y, zb1);
            zc1 = fmaf(wz.z, a1.z, zc1); zd1 = fmaf(wz.w, a1.w, zd1);
            ra0 = fmaf(wr.x, a0.x, ra0); rb0 = fmaf(wr.y, a0.y, rb0);
            rc0 = fmaf(wr.z, a0.z, rc0); rd0 = fmaf(wr.w, a0.w, rd0);
            ra1 = fmaf(wr.x, a1.x, ra1); rb1 = fmaf(wr.y, a1.y, rb1);
            rc1 = fmaf(wr.z, a1.z, rc1); rd1 = fmaf(wr.w, a1.w, rd1);
        }
        float z0 = sigf((za0 + zb0) + (zc0 + zd0));
        float z1 = sigf((za1 + zb1) + (zc1 + zd1));
        float r0 = sigf((ra0 + rb0) + (rc0 + rd0));
        float r1 = sigf((ra1 + rb1) + (rc1 + rd1));

        hp[tid] = r0 * hh0;
        hp[128 + tid] = r1 * hh1;
        __syncthreads();

        // h_tilde GEMV
        float ta0 = ah0, tb0 = 0.f, tc0 = 0.f, td0 = 0.f;
        float ta1 = ah1, tb1 = 0.f, tc1 = 0.f, td1 = 0.f;
        const float4* p0v = (const float4*)hp;
        const float4* p1v = (const float4*)(hp + 128);
#pragma unroll
        for (int k4 = 0; k4 < 32; ++k4) {
            float4 wh = wh4[k4];
            float4 a0 = p0v[k4], a1 = p1v[k4];
            ta0 = fmaf(wh.x, a0.x, ta0); tb0 = fmaf(wh.y, a0.y, tb0);
            tc0 = fmaf(wh.z, a0.z, tc0); td0 = fmaf(wh.w, a0.w, td0);
            ta1 = fmaf(wh.x, a1.x, ta1); tb1 = fmaf(wh.y, a1.y, tb1);
            tc1 = fmaf(wh.z, a1.z, tc1); td1 = fmaf(wh.w, a1.w, td1);
        }
        float ht0 = tanhfast((ta0 + tb0) + (tc0 + td0));
        float ht1 = tanhfast((ta1 + tb1) + (tc1 + td1));

        h0 = (1.f - z0) * hh0 + z0 * ht0;
        h1 = (1.f - z1) * hh1 + z1 * ht1;

        hs[((size_t)b0 * T_ + t) * 128 + tid] = h0;
        hs[((size_t)b1 * T_ + t) * 128 + tid] = h1;

        gh0 = ngh0; az0 = naz0; ar0 = nar0; ah0 = nah0;
        gh1 = ngh1; az1 = naz1; ar1 = nar1; ah1 = nah1;
    }
}

// ---------------- y = sigmoid(hs @ W_hy + b_hy) ----------------------------
// A row-major (B*T, 128); block: 128 rows x 64 cols.
__global__ __launch_bounds__(256)
void gemmY_kernel(const float* __restrict__ Why, const float* __restrict__ bhy,
                  float* __restrict__ out) {
    __shared__ float As[16 * 132];
    __shared__ float Bs[16 * 64];
    const float* A = out + (size_t)B_ * T_ * OUT_;  // hs region
    size_t r0 = (size_t)blockIdx.x * 128;
    int tid = threadIdx.x;
    int ty = tid >> 4, tx = tid & 15;

    float acc[8][4];
#pragma unroll
    for (int i = 0; i < 8; i++)
#pragma unroll
        for (int j = 0; j < 4; j++) acc[i][j] = 0.0f;

    for (int kbase = 0; kbase < 128; kbase += 16) {
        // load A tile: 128 rows x 16 k, float4 along k
        {
            int row = tid >> 2, c = tid & 3;
#pragma unroll
            for (int rr = 0; rr < 2; ++rr) {
                int r = row + rr * 64;
                float4 av = *(const float4*)(A + (r0 + r) * 128 + kbase + c * 4);
                As[(c * 4 + 0) * 132 + r] = av.x;
                As[(c * 4 + 1) * 132 + r] = av.y;
                As[(c * 4 + 2) * 132 + r] = av.z;
                As[(c * 4 + 3) * 132 + r] = av.w;
            }
        }
        {
            int f_l = tid >> 4, v = tid & 15;
            *(float4*)&Bs[f_l * 64 + v * 4] =
                *(const float4*)(Why + (size_t)(kbase + f_l) * 64 + v * 4);
        }
        __syncthreads();
#pragma unroll
        for (int kk = 0; kk < 16; ++kk) {
            float4 a0q = *(float4*)&As[kk * 132 + ty * 8];
            float4 a1q = *(float4*)&As[kk * 132 + ty * 8 + 4];
            float4 bq  = *(float4*)&Bs[kk * 64 + tx * 4];
            float a[8] = {a0q.x, a0q.y, a0q.z, a0q.w, a1q.x, a1q.y, a1q.z, a1q.w};
            float bb[4] = {bq.x, bq.y, bq.z, bq.w};
#pragma unroll
            for (int i = 0; i < 8; i++)
#pragma unroll
                for (int j = 0; j < 4; j++) acc[i][j] = fmaf(a[i], bb[j], acc[i][j]);
        }
        __syncthreads();
    }
    float bl[4];
#pragma unroll
    for (int j = 0; j < 4; j++) bl[j] = bhy[tx * 4 + j];
#pragma unroll
    for (int i = 0; i < 8; i++) {
        size_t rg = r0 + ty * 8 + i;
        float4 vo;
        vo.x = sigf(acc[i][0] + bl[0]);
        vo.y = sigf(acc[i][1] + bl[1]);
        vo.z = sigf(acc[i][2] + bl[2]);
        vo.w = sigf(acc[i][3] + bl[3]);
        *(float4*)(out + rg * 64 + tx * 4) = vo;
    }
}

// ---------------- launch ----------------------------------------------------
extern "C" void kernel_launch(void* const* d_in, const int* in_sizes, int n_in,
                              void* d_out, int out_size) {
    const float* input  = (const float*)d_in[0];
    const float* x_mean = (const float*)d_in[1];
    const float* W_dg_x = (const float*)d_in[2];
    const float* b_dg_x = (const float*)d_in[3];
    const float* W_dg_h = (const float*)d_in[4];
    const float* b_dg_h = (const float*)d_in[5];
    const float* W_xz   = (const float*)d_in[6];
    const float* W_hz   = (const float*)d_in[7];
    const float* W_mz   = (const float*)d_in[8];
    const float* b_mz   = (const float*)d_in[9];
    const float* W_xr   = (const float*)d_in[10];
    const float* W_hr   = (const float*)d_in[11];
    const float* W_mr   = (const float*)d_in[12];
    const float* W_xh   = (const float*)d_in[13];
    const float* W_hh   = (const float*)d_in[14];
    const float* W_mh   = (const float*)d_in[15];
    const float* b_mh   = (const float*)d_in[16];
    const float* W_hy   = (const float*)d_in[17];
    const float* b_hy   = (const float*)d_in[18];
    float* out = (float*)d_out;

    static bool attr_set = false;
    if (!attr_set) {
        cudaFuncSetAttribute(recur_kernel, cudaFuncAttributeMaxDynamicSharedMemorySize, 211000);
        attr_set = true;
    }

    pack_kernel<<<1, 256>>>(W_xz, W_mz, b_mz, W_xr, W_mr, W_xh, W_mh, b_mh);

    // gamma_x: K=64, N=64 -> g_gxT (b,n,t)
    gemmT_kernel<<<dim3(1, 8, B_), 256>>>(input, W_dg_x, 64, b_dg_x,
                                          64, /*act*/1, /*out*/1, 0, /*src*/0);
    // gamma_h: K=64, N=128 -> g_act[0:128)
    gemmT_kernel<<<dim3(2, 8, B_), 256>>>(input, W_dg_h, 128, b_dg_h,
                                          64, 1, 0, 0, 0);
    // LOCF scan -> g_xeff
    scan_kernel<<<64, 256>>>(input, x_mean);
    // A_zrh: K=128, N=384 -> g_act[128:512)
    gemmT_kernel<<<dim3(6, 8, B_), 256>>>(input, nullptr, 384, nullptr,
                                          128, 0, 0, 128, 1);
    // recurrence -> hs region of d_out
    recur_kernel<<<128, 128, 206848>>>(W_hz, W_hr, W_hh, out);
    // y -> ys region of d_out
    gemmY_kernel<<<(B_ * T_) / 128, 256>>>(W_hy, b_hy, out);
}